// round 13
// baseline (speedup 1.0000x reference)
#include <cuda_runtime.h>
#include <cstdint>

#define NFFT   512
#define HOPSZ  160
#define PADN   256
#define BVAL   32
#define TVAL   1024
#define FBINS  257
#define LTRIM  163680                  // (TVAL-1)*HOPSZ
#define OUTLEN 164192                  // NFFT + HOPSZ*(TVAL-1)
#define NITER  32
#define TOTF   (BVAL*TVAL*FBINS)       // 8421376
#define NFRAMES (BVAL*TVAL)            // 32768
#define Z4TOT  ((BVAL*OUTLEN)/4)       // 1313536 float4
#define PI_F 3.14159265358979323846f
#define RSQ2 0.70710678118654752440f

// ---------------- scratch (device globals; no allocation allowed) ------------
__device__ float4 g_ya4[Z4TOT];                        // waveform A (raw), 21 MB
__device__ float4 g_yb4[Z4TOT];                        // waveform B (raw), 21 MB
__device__ float4 g_yc4[Z4TOT];                        // waveform C (raw), 21 MB
__device__ float2 g_ph[TOTF];                          // init phasor fp32, 67 MB
__device__ float  g_invwsq[OUTLEN];                    // NOLA 1/wsq (guarded)
__device__ float2 g_tw[256];                           // e^{+2*pi*i*k/256}
__device__ float2 g_pk[FBINS];                         // (cos(pi k/256), sin(pi k/256))

// ---------------- packed f32x2 helpers (FADD2 / FFMA2) -----------------------
__device__ __forceinline__ unsigned long long f2u(float2 a) {
    unsigned long long r;
    asm("mov.b64 %0, {%1, %2};" : "=l"(r) : "f"(a.x), "f"(a.y));
    return r;
}
__device__ __forceinline__ float2 u2f(unsigned long long u) {
    float2 a;
    asm("mov.b64 {%0, %1}, %2;" : "=f"(a.x), "=f"(a.y) : "l"(u));
    return a;
}
// a + b, packed
__device__ __forceinline__ float2 padd(float2 a, float2 b) {
    unsigned long long r, ua = f2u(a), ub = f2u(b);
    asm("add.rn.f32x2 %0, %1, %2;" : "=l"(r) : "l"(ua), "l"(ub));
    return u2f(r);
}
// a*b + c elementwise, packed
__device__ __forceinline__ float2 pfma(float2 a, float2 b, float2 c) {
    unsigned long long r, ua = f2u(a), ub = f2u(b), uc = f2u(c);
    asm("fma.rn.f32x2 %0, %1, %2, %3;" : "=l"(r) : "l"(ua), "l"(ub), "l"(uc));
    return u2f(r);
}
__device__ __forceinline__ float2 psub(float2 a, float2 b) {    // a - b
    return pfma(b, make_float2(-1.f, -1.f), a);
}

__device__ __forceinline__ float2 cmulf(float2 a, float2 b) {
    return make_float2(a.x * b.x - a.y * b.y, a.x * b.y + a.y * b.x);
}
template <int SGN>
__device__ __forceinline__ float2 cmuli(float2 a) {   // SGN * i * a
    return (SGN > 0) ? make_float2(-a.y, a.x) : make_float2(a.y, -a.x);
}

// padded smem index: +1 float2 every 16 to break stride-8/16 conflicts
#define IDXP(i) ((i) + ((i) >> 4))
#define SBUF 272

// ---------------------------------------------------------------------------
// 256-pt complex FFT, one warp per transform, 8 complex points per lane.
// Input:  v[j] = x[l + 32*j] (natural order); Output: v[j] = X[j + 8*brev5(l)]
// SGN = -1 forward, +1 inverse (unnormalized). Butterfly adds use packed f32x2.
// ---------------------------------------------------------------------------
template <int SGN>
__device__ __forceinline__ void fft256_warp(float2 v[8], int l) {
    // ---- radix-8 over j (stride-32 dim), registers, packed adds ----
    float2 t0 = v[0], t1 = v[4], t2 = v[2], t3 = v[6];
    float2 t4 = v[1], t5 = v[5], t6 = v[3], t7 = v[7];
    float2 a0 = padd(t0, t1), a1 = psub(t0, t1);
    float2 a2 = padd(t2, t3), a3 = psub(t2, t3);
    float2 a4 = padd(t4, t5), a5 = psub(t4, t5);
    float2 a6 = padd(t6, t7), a7 = psub(t6, t7);
    float2 i3 = cmuli<SGN>(a3), i7 = cmuli<SGN>(a7);
    float2 b0 = padd(a0, a2), b2 = psub(a0, a2);
    float2 b1 = padd(a1, i3), b3 = psub(a1, i3);
    float2 b4 = padd(a4, a6), b6 = psub(a4, a6);
    float2 b5 = padd(a5, i7), b7 = psub(a5, i7);
    float2 u1 = make_float2(RSQ2 * (b5.x - (float)SGN * b5.y),
                            RSQ2 * (b5.y + (float)SGN * b5.x));
    float2 u2 = cmuli<SGN>(b6);
    float2 u3 = make_float2(-RSQ2 * (b7.x + (float)SGN * b7.y),
                             RSQ2 * ((float)SGN * b7.x - b7.y));
    v[0] = padd(b0, b4);  v[4] = psub(b0, b4);
    v[1] = padd(b1, u1);  v[5] = psub(b1, u1);
    v[2] = padd(b2, u2);  v[6] = psub(b2, u2);
    v[3] = padd(b3, u3);  v[7] = psub(b3, u3);

    // ---- twiddle e^{SGN*2*pi*i*l*k1/256} via power chain (scalar cmul) ----
    float2 w1 = g_tw[l];
    if (SGN < 0) w1.y = -w1.y;
    float2 w = w1;
    v[1] = cmulf(v[1], w);
#pragma unroll
    for (int k1 = 2; k1 < 8; k1++) {
        w = cmulf(w, w1);
        v[k1] = cmulf(v[k1], w);
    }

    // ---- cross-lane 32-pt FFT: 5 xor-shfl rounds, 2 cmul rounds ----
    const int lb4 = (l >> 4) & 1, lb3 = (l >> 3) & 1;
    const int lb2 = (l >> 2) & 1, lb1 = (l >> 1) & 1, lb0 = l & 1;

    {   // Round 1: xor 16; lanes (b4&b3) pick up W32^8 = SGN*i
        const float p = lb4 ? -1.f : 1.f;
        const float2 pp = make_float2(p, p);
        const bool rot = (lb4 & lb3) != 0;
#pragma unroll
        for (int j = 0; j < 8; j++) {
            float2 o = v[j];
            float2 t;
            t.x = __shfl_xor_sync(0xffffffffu, o.x, 16);
            t.y = __shfl_xor_sync(0xffffffffu, o.y, 16);
            float2 q = pfma(o, pp, t);
            v[j] = rot ? cmuli<SGN>(q) : q;
        }
    }
    {   // Round 2: xor 8; combined twiddle W32^{(l&7)*e1}, e1 = b4+2*b3
        const float p = lb3 ? -1.f : 1.f;
        const float2 pp = make_float2(p, p);
        const int e1 = lb4 + 2 * lb3;
        float2 tw = g_tw[((l & 7) * e1) << 3];
        if (SGN < 0) tw.y = -tw.y;
#pragma unroll
        for (int j = 0; j < 8; j++) {
            float2 o = v[j];
            float2 t;
            t.x = __shfl_xor_sync(0xffffffffu, o.x, 8);
            t.y = __shfl_xor_sync(0xffffffffu, o.y, 8);
            v[j] = cmulf(pfma(o, pp, t), tw);
        }
    }
    {   // Round 3: xor 4; lanes (b2&b1) pick up W8^2 = SGN*i
        const float p = lb2 ? -1.f : 1.f;
        const float2 pp = make_float2(p, p);
        const bool rot = (lb2 & lb1) != 0;
#pragma unroll
        for (int j = 0; j < 8; j++) {
            float2 o = v[j];
            float2 t;
            t.x = __shfl_xor_sync(0xffffffffu, o.x, 4);
            t.y = __shfl_xor_sync(0xffffffffu, o.y, 4);
            float2 q = pfma(o, pp, t);
            v[j] = rot ? cmuli<SGN>(q) : q;
        }
    }
    {   // Round 4: xor 2; combined twiddle W8^{b0*e2}, e2 = b2+2*b1
        const float p = lb1 ? -1.f : 1.f;
        const float2 pp = make_float2(p, p);
        const int e2 = lb2 + 2 * lb1;
        float2 tw = g_tw[(lb0 * e2) << 5];
        if (SGN < 0) tw.y = -tw.y;
#pragma unroll
        for (int j = 0; j < 8; j++) {
            float2 o = v[j];
            float2 t;
            t.x = __shfl_xor_sync(0xffffffffu, o.x, 2);
            t.y = __shfl_xor_sync(0xffffffffu, o.y, 2);
            v[j] = cmulf(pfma(o, pp, t), tw);
        }
    }
    {   // Round 5: xor 1, no twiddle
        const float p = lb0 ? -1.f : 1.f;
        const float2 pp = make_float2(p, p);
#pragma unroll
        for (int j = 0; j < 8; j++) {
            float2 o = v[j];
            float2 t;
            t.x = __shfl_xor_sync(0xffffffffu, o.x, 1);
            t.y = __shfl_xor_sync(0xffffffffu, o.y, 1);
            v[j] = pfma(o, pp, t);
        }
    }
}

__device__ __forceinline__ int brev5(int l) { return (int)(__brev((unsigned)l) >> 27); }

// ---------------------------------------------------------------------------
__global__ void k_tables() {
    int k = threadIdx.x;
    if (k < 256) {
        float a = (2.0f * PI_F) * (float)k / 256.0f;
        g_tw[k] = make_float2(cosf(a), sinf(a));
    }
    if (k < FBINS) {
        float b = PI_F * (float)k / 256.0f;
        g_pk[k] = make_float2(cosf(b), sinf(b));
    }
}

__global__ void k_invwsq(const float* __restrict__ win) {
    int i = blockIdx.x * blockDim.x + threadIdx.x;
    if (i >= OUTLEN) return;
    int tmax = i / HOPSZ;             if (tmax > TVAL - 1) tmax = TVAL - 1;
    int tmin = (i - (NFFT - 1) + HOPSZ - 1) / HOPSZ;  if (tmin < 0) tmin = 0;
    float s = 0.f;
    for (int t = tmin; t <= tmax; t++) {
        int n = i - t * HOPSZ;
        if (n >= 0 && n < NFFT) { float w = win[n]; s += w * w; }
    }
    g_invwsq[i] = (s > 1e-11f) ? (1.0f / s) : 1.0f;
}

// init phasor + zero buffer A (same launch; A used only by the NEXT kernel)
__global__ void k_init_ph(const float* __restrict__ ang, float4* __restrict__ yz) {
    int i = blockIdx.x * blockDim.x + threadIdx.x;
    if (i < Z4TOT) yz[i] = make_float4(0.f, 0.f, 0.f, 0.f);
    if (i < TOTF) {
        float s, c;
        sincosf(ang[i], &s, &c);
        g_ph[i] = make_float2(c, s);
    }
}

// ---------------------------------------------------------------------------
// ISTFT (init only): spec = mag * phasor -> irfft -> window -> atomic OLA
// also zeroes buffer `yz` (dst of the first GL step)
// ---------------------------------------------------------------------------
__global__ __launch_bounds__(256) void k_istft(const float* __restrict__ mag,
                                               const float* __restrict__ win,
                                               float* __restrict__ y,
                                               float4* __restrict__ yz) {
    __shared__ float2 sw[8][SBUF];
    const int wid = threadIdx.x >> 5;
    const int l   = threadIdx.x & 31;
    const int frame = (blockIdx.x << 3) + wid;
    const int b = frame >> 10;
    const int t = frame & 1023;
    const float*  magp = mag  + (size_t)frame * FBINS;
    const float2* php  = g_ph + (size_t)frame * FBINS;

    // zero the spare buffer (no hazard: different buffer, used next launch)
    for (int i = blockIdx.x * blockDim.x + threadIdx.x; i < Z4TOT;
         i += gridDim.x * blockDim.x)
        yz[i] = make_float4(0.f, 0.f, 0.f, 0.f);

    float2 v[8];
#pragma unroll
    for (int j = 0; j < 8; j++) {
        int k  = l + (j << 5);
        int kr = 256 - k;
        float  mk = magp[k];
        float  mr = magp[kr];
        float2 pk = php[k];
        float2 pr = php[kr];
        float Xkx = mk * pk.x, Xky = mk * pk.y;
        float Xcx = mr * pr.x, Xcy = -mr * pr.y;   // conj(X[256-k])
        if (k == 0) { Xky = 0.f; Xcy = 0.f; }
        float Zex = 0.5f * (Xkx + Xcx), Zey = 0.5f * (Xky + Xcy);
        float Bx  = 0.5f * (Xkx - Xcx), By  = 0.5f * (Xky - Xcy);
        float2 e = g_pk[k];
        float Zox = Bx * e.x - By * e.y;
        float Zoy = Bx * e.y + By * e.x;
        v[j] = make_float2(Zex - Zoy, Zey + Zox);
    }
    fft256_warp<1>(v, l);

    const int r8 = brev5(l) << 3;
#pragma unroll
    for (int j = 0; j < 8; j++) sw[wid][IDXP(j + r8)] = v[j];
    __syncwarp();

    float* yb = y + (size_t)b * OUTLEN + t * HOPSZ;
    const float2* w2p = (const float2*)win;
#pragma unroll
    for (int j = 0; j < 8; j++) {
        int m = l + (j << 5);
        float2 z = sw[wid][IDXP(m)];
        float2 w = w2p[m];
        atomicAdd(yb + 2 * m,     z.x * (1.0f / 256.0f) * w.x);
        atomicAdd(yb + 2 * m + 1, z.y * (1.0f / 256.0f) * w.y);
    }
}

// ---------------------------------------------------------------------------
// Fused Griffin-Lim step, one frame per warp:
// gather(y_src) -> rfft -> phase+remag (registers) -> irfft -> scatter(y_dst)
// also zeroes the spare buffer `yz` (dst of the NEXT iteration)
// ---------------------------------------------------------------------------
__device__ __forceinline__ float sample_at(const float* yb, int i) {
    int j = i - PADN;
    j = (j < 0) ? -j : j;
    if (j >= LTRIM) j = 2 * LTRIM - 2 - j;
    int idx = j + PADN;
    return yb[idx] * g_invwsq[idx];
}

__device__ __forceinline__ float2 scaled_norm(float x, float y, float m) {
    float m2 = x * x + y * y;
    if (m2 < 1e-30f) return make_float2(m, 0.f);  // atan2(0,0)=0 -> phase (1,0)
    float inv = m * rsqrtf(m2);
    return make_float2(x * inv, y * inv);
}

__global__ __launch_bounds__(256) void k_gl_step(const float* __restrict__ mag,
                                                 const float* __restrict__ win,
                                                 const float* __restrict__ ysrc,
                                                 float* __restrict__ ydst,
                                                 float4* __restrict__ yz) {
    __shared__ float2 sw[8][SBUF];
    const int wid = threadIdx.x >> 5;
    const int l   = threadIdx.x & 31;
    const int frame = (blockIdx.x << 3) + wid;
    const int b = frame >> 10;
    const int t = frame & 1023;
    const float* magp = mag + (size_t)frame * FBINS;
    const float* ysb  = ysrc + (size_t)b * OUTLEN;
    const int i0 = t * HOPSZ;
    const float2* w2p = (const float2*)win;

    // zero the spare buffer for the next iteration (idle this launch)
    for (int i = blockIdx.x * blockDim.x + threadIdx.x; i < Z4TOT;
         i += gridDim.x * blockDim.x)
        yz[i] = make_float4(0.f, 0.f, 0.f, 0.f);

    // ---- STFT gather (fast path for interior frames) ----
    float2 v[8];
    if (t >= 2 && t <= 1021) {
        const float2* src = (const float2*)(ysb + i0);
        const float2* iwp = (const float2*)(g_invwsq + i0);
#pragma unroll
        for (int j = 0; j < 8; j++) {
            int m = l + (j << 5);
            float2 xy = src[m];
            float2 iw = iwp[m];
            float2 w  = w2p[m];
            v[j] = make_float2(xy.x * iw.x * w.x, xy.y * iw.y * w.y);
        }
    } else {
#pragma unroll
        for (int j = 0; j < 8; j++) {
            int m  = l + (j << 5);
            int n0 = 2 * m;
            float x0 = sample_at(ysb, i0 + n0);
            float x1 = sample_at(ysb, i0 + n0 + 1);
            float2 w = w2p[m];
            v[j] = make_float2(x0 * w.x, x1 * w.y);
        }
    }
    fft256_warp<-1>(v, l);   // forward

    const int r8 = brev5(l) << 3;
#pragma unroll
    for (int j = 0; j < 8; j++) sw[wid][IDXP(j + r8)] = v[j];
    __syncwarp();

    // ---- phase + re-magnitude + inverse pack, all in registers ----
#pragma unroll
    for (int j = 0; j < 8; j++) {
        int k = l + (j << 5);
        if (k == 0) {
            float2 Z0 = sw[wid][IDXP(0)];
            float X0 = Z0.x + Z0.y;       // X[0]   (real)
            float XN = Z0.x - Z0.y;       // X[256] (real)
            float A = (X0 >= 0.f) ? magp[0]   : -magp[0];
            float C = (XN >= 0.f) ? magp[256] : -magp[256];
            v[j] = make_float2(0.5f * (A + C), 0.5f * (A - C));
        } else {
            float2 Zk = sw[wid][IDXP(k)];
            float2 Zr = sw[wid][IDXP(256 - k)];
            float Zex = 0.5f * (Zk.x + Zr.x);
            float Zey = 0.5f * (Zk.y - Zr.y);
            float Zox = 0.5f * (Zk.y + Zr.y);
            float Zoy = -0.5f * (Zk.x - Zr.x);
            float2 e = g_pk[k];
            float Tx = Zox * e.x + Zoy * e.y;     // Zo * conj(e)
            float Ty = Zoy * e.x - Zox * e.y;
            float2 A = scaled_norm(Zex + Tx, Zey + Ty, magp[k]);
            float2 C = scaled_norm(Zex - Tx, Zey - Ty, magp[256 - k]);
            float Pex = 0.5f * (A.x + C.x), Pey = 0.5f * (A.y + C.y);
            float Bx  = 0.5f * (A.x - C.x), By  = 0.5f * (A.y - C.y);
            float Qx = Bx * e.x - By * e.y;
            float Qy = Bx * e.y + By * e.x;
            v[j] = make_float2(Pex - Qy, Pey + Qx);
        }
    }
    __syncwarp();   // all sw reads done before overwrite below

    fft256_warp<1>(v, l);   // inverse, unnormalized

#pragma unroll
    for (int j = 0; j < 8; j++) sw[wid][IDXP(j + r8)] = v[j];
    __syncwarp();

    float* yd = ydst + (size_t)b * OUTLEN + t * HOPSZ;
#pragma unroll
    for (int j = 0; j < 8; j++) {
        int m = l + (j << 5);
        float2 z = sw[wid][IDXP(m)];
        float2 w = w2p[m];
        atomicAdd(yd + 2 * m,     z.x * (1.0f / 256.0f) * w.x);
        atomicAdd(yd + 2 * m + 1, z.y * (1.0f / 256.0f) * w.y);
    }
}

__global__ void k_out(const float* __restrict__ y, float* __restrict__ out) {
    int i = blockIdx.x * blockDim.x + threadIdx.x;
    if (i < BVAL * LTRIM) {
        int b = i / LTRIM;
        int r = i - b * LTRIM;
        int idx = PADN + r;
        out[i] = y[(size_t)b * OUTLEN + idx] * g_invwsq[idx];
    }
}

// ---------------------------------------------------------------------------
extern "C" void kernel_launch(void* const* d_in, const int* in_sizes, int n_in,
                              void* d_out, int out_size) {
    const float* mag = (const float*)d_in[0];   // [32,1024,257]
    const float* ang = (const float*)d_in[1];   // [32,1024,257]
    const float* win = (const float*)d_in[2];   // [512]
    float* out = (float*)d_out;                 // [32,163680]

    float* buf[3];
    cudaGetSymbolAddress((void**)&buf[0], g_ya4);
    cudaGetSymbolAddress((void**)&buf[1], g_yb4);
    cudaGetSymbolAddress((void**)&buf[2], g_yc4);

    k_tables<<<1, FBINS>>>();
    k_invwsq<<<(OUTLEN + 255) / 256, 256>>>(win);
    k_init_ph<<<TOTF / 256, 256>>>(ang, (float4*)buf[0]);   // phasor + zero A

    const int fgrid = NFRAMES / 8;   // 8 frames (warps) per block

    // y_0 = istft(mag * e^{i*ang}) into A; zero B (dst of iter 0)
    k_istft<<<fgrid, 256>>>(mag, win, buf[0], (float4*)buf[1]);

    for (int it = 0; it < NITER; it++) {
        float* src = buf[it % 3];
        float* dst = buf[(it + 1) % 3];
        float* spr = buf[(it + 2) % 3];   // zeroed this launch, dst next iter
        k_gl_step<<<fgrid, 256>>>(mag, win, src, dst, (float4*)spr);
    }
    // final waveform is in buf[NITER % 3] = buf[2]
    k_out<<<(BVAL * LTRIM + 255) / 256, 256>>>(buf[NITER % 3], out);
}

// round 14
// speedup vs baseline: 1.6051x; 1.6051x over previous
#include <cuda_runtime.h>
#include <cstdint>

#define NFFT   512
#define HOPSZ  160
#define PADN   256
#define BVAL   32
#define TVAL   1024
#define FBINS  257
#define LTRIM  163680                  // (TVAL-1)*HOPSZ
#define OUTLEN 164192                  // NFFT + HOPSZ*(TVAL-1)
#define NITER  32
#define TOTF   (BVAL*TVAL*FBINS)       // 8421376
#define NFRAMES (BVAL*TVAL)            // 32768
#define PI_F 3.14159265358979323846f
#define RSQ2 0.70710678118654752440f

// ---------------- scratch (device globals; no allocation allowed) ------------
__device__ float4 g_ya4[(BVAL * OUTLEN) / 4];          // waveform ping (raw), 21 MB
__device__ float4 g_yb4[(BVAL * OUTLEN) / 4];          // waveform pong (raw), 21 MB
__device__ float2 g_ph[TOTF];                          // init phasor fp32, 67 MB
__device__ float  g_invwsq[OUTLEN];                    // NOLA 1/wsq (guarded)
__device__ float2 g_wsc[256];                          // win/256 pairs (scatter)
__device__ float2 g_tw[256];                           // e^{+2*pi*i*k/256}
__device__ float2 g_pk[FBINS];                         // (cos(pi k/256), sin(pi k/256))

__device__ __forceinline__ float2 cmulf(float2 a, float2 b) {
    return make_float2(a.x * b.x - a.y * b.y, a.x * b.y + a.y * b.x);
}
__device__ __forceinline__ float2 cadd(float2 a, float2 b) {
    return make_float2(a.x + b.x, a.y + b.y);
}
__device__ __forceinline__ float2 csub(float2 a, float2 b) {
    return make_float2(a.x - b.x, a.y - b.y);
}
template <int SGN>
__device__ __forceinline__ float2 cmuli(float2 a) {   // SGN * i * a
    return (SGN > 0) ? make_float2(-a.y, a.x) : make_float2(a.y, -a.x);
}

// one red.global.add.v2.f32 instead of two scalar atomics (addr 8B-aligned)
__device__ __forceinline__ void red_add_v2(float* addr, float x, float y) {
    asm volatile("red.global.add.v2.f32 [%0], {%1, %2};"
                 :: "l"(addr), "f"(x), "f"(y) : "memory");
}

// padded smem index: +1 float2 every 16 to break stride-8/16 conflicts
#define IDXP(i) ((i) + ((i) >> 4))
#define SBUF 272

// ---------------------------------------------------------------------------
// 256-pt complex FFT, one warp per transform, 8 complex points per lane.
// Input:  v[j] = x[l + 32*j] (natural order); Output: v[j] = X[j + 8*brev5(l)]
// SGN = -1 forward, +1 inverse (unnormalized). Cross-lane 32-pt FFT:
// fused radix-4/radix-4/radix-2 with deferred twiddles (2 cmul rounds).
// ---------------------------------------------------------------------------
template <int SGN>
__device__ __forceinline__ void fft256_warp(float2 v[8], int l) {
    // ---- radix-8 over j (stride-32 dim), registers ----
    float2 t0 = v[0], t1 = v[4], t2 = v[2], t3 = v[6];
    float2 t4 = v[1], t5 = v[5], t6 = v[3], t7 = v[7];
    float2 a0 = cadd(t0, t1), a1 = csub(t0, t1);
    float2 a2 = cadd(t2, t3), a3 = csub(t2, t3);
    float2 a4 = cadd(t4, t5), a5 = csub(t4, t5);
    float2 a6 = cadd(t6, t7), a7 = csub(t6, t7);
    float2 i3 = cmuli<SGN>(a3), i7 = cmuli<SGN>(a7);
    float2 b0 = cadd(a0, a2), b2 = csub(a0, a2);
    float2 b1 = cadd(a1, i3), b3 = csub(a1, i3);
    float2 b4 = cadd(a4, a6), b6 = csub(a4, a6);
    float2 b5 = cadd(a5, i7), b7 = csub(a5, i7);
    float2 u1 = make_float2(RSQ2 * (b5.x - (float)SGN * b5.y),
                            RSQ2 * (b5.y + (float)SGN * b5.x));
    float2 u2 = cmuli<SGN>(b6);
    float2 u3 = make_float2(-RSQ2 * (b7.x + (float)SGN * b7.y),
                             RSQ2 * ((float)SGN * b7.x - b7.y));
    v[0] = cadd(b0, b4);  v[4] = csub(b0, b4);
    v[1] = cadd(b1, u1);  v[5] = csub(b1, u1);
    v[2] = cadd(b2, u2);  v[6] = csub(b2, u2);
    v[3] = cadd(b3, u3);  v[7] = csub(b3, u3);

    // ---- twiddle e^{SGN*2*pi*i*l*k1/256} via power chain ----
    float2 w1 = g_tw[l];
    if (SGN < 0) w1.y = -w1.y;
    float2 w = w1;
    v[1] = cmulf(v[1], w);
#pragma unroll
    for (int k1 = 2; k1 < 8; k1++) {
        w = cmulf(w, w1);
        v[k1] = cmulf(v[k1], w);
    }

    // ---- cross-lane 32-pt FFT: 5 xor-shfl rounds, 2 cmul rounds ----
    const int lb4 = (l >> 4) & 1, lb3 = (l >> 3) & 1;
    const int lb2 = (l >> 2) & 1, lb1 = (l >> 1) & 1, lb0 = l & 1;

    {   // Round 1: xor 16; lanes (b4&b3) pick up W32^8 = SGN*i
        const float p = lb4 ? -1.f : 1.f;
        const bool rot = (lb4 & lb3) != 0;
#pragma unroll
        for (int j = 0; j < 8; j++) {
            float2 o = v[j];
            float tx = __shfl_xor_sync(0xffffffffu, o.x, 16);
            float ty = __shfl_xor_sync(0xffffffffu, o.y, 16);
            float2 q = make_float2(tx + p * o.x, ty + p * o.y);
            v[j] = rot ? cmuli<SGN>(q) : q;
        }
    }
    {   // Round 2: xor 8; combined twiddle W32^{(l&7)*e1}, e1 = b4+2*b3
        const float p = lb3 ? -1.f : 1.f;
        const int e1 = lb4 + 2 * lb3;
        float2 tw = g_tw[((l & 7) * e1) << 3];
        if (SGN < 0) tw.y = -tw.y;
#pragma unroll
        for (int j = 0; j < 8; j++) {
            float2 o = v[j];
            float tx = __shfl_xor_sync(0xffffffffu, o.x, 8);
            float ty = __shfl_xor_sync(0xffffffffu, o.y, 8);
            float2 q = make_float2(tx + p * o.x, ty + p * o.y);
            v[j] = cmulf(q, tw);
        }
    }
    {   // Round 3: xor 4; lanes (b2&b1) pick up W8^2 = SGN*i
        const float p = lb2 ? -1.f : 1.f;
        const bool rot = (lb2 & lb1) != 0;
#pragma unroll
        for (int j = 0; j < 8; j++) {
            float2 o = v[j];
            float tx = __shfl_xor_sync(0xffffffffu, o.x, 4);
            float ty = __shfl_xor_sync(0xffffffffu, o.y, 4);
            float2 q = make_float2(tx + p * o.x, ty + p * o.y);
            v[j] = rot ? cmuli<SGN>(q) : q;
        }
    }
    {   // Round 4: xor 2; combined twiddle W8^{b0*e2}, e2 = b2+2*b1
        const float p = lb1 ? -1.f : 1.f;
        const int e2 = lb2 + 2 * lb1;
        float2 tw = g_tw[(lb0 * e2) << 5];
        if (SGN < 0) tw.y = -tw.y;
#pragma unroll
        for (int j = 0; j < 8; j++) {
            float2 o = v[j];
            float tx = __shfl_xor_sync(0xffffffffu, o.x, 2);
            float ty = __shfl_xor_sync(0xffffffffu, o.y, 2);
            float2 q = make_float2(tx + p * o.x, ty + p * o.y);
            v[j] = cmulf(q, tw);
        }
    }
    {   // Round 5: xor 1, no twiddle
        const float p = lb0 ? -1.f : 1.f;
#pragma unroll
        for (int j = 0; j < 8; j++) {
            float2 o = v[j];
            float tx = __shfl_xor_sync(0xffffffffu, o.x, 1);
            float ty = __shfl_xor_sync(0xffffffffu, o.y, 1);
            v[j] = make_float2(tx + p * o.x, ty + p * o.y);
        }
    }
}

__device__ __forceinline__ int brev5(int l) { return (int)(__brev((unsigned)l) >> 27); }

// ---------------------------------------------------------------------------
__global__ void k_tables() {
    int k = threadIdx.x;
    if (k < 256) {
        float a = (2.0f * PI_F) * (float)k / 256.0f;
        g_tw[k] = make_float2(cosf(a), sinf(a));
    }
    if (k < FBINS) {
        float b = PI_F * (float)k / 256.0f;
        g_pk[k] = make_float2(cosf(b), sinf(b));
    }
}

__global__ void k_invwsq(const float* __restrict__ win) {
    int i = blockIdx.x * blockDim.x + threadIdx.x;
    if (i < 256)    // prescaled scatter window: win/256 as float2 pairs
        g_wsc[i] = make_float2(win[2 * i] * (1.0f / 256.0f),
                               win[2 * i + 1] * (1.0f / 256.0f));
    if (i >= OUTLEN) return;
    int tmax = i / HOPSZ;             if (tmax > TVAL - 1) tmax = TVAL - 1;
    int tmin = (i - (NFFT - 1) + HOPSZ - 1) / HOPSZ;  if (tmin < 0) tmin = 0;
    float s = 0.f;
    for (int t = tmin; t <= tmax; t++) {
        int n = i - t * HOPSZ;
        if (n >= 0 && n < NFFT) { float w = win[n]; s += w * w; }
    }
    g_invwsq[i] = (s > 1e-11f) ? (1.0f / s) : 1.0f;
}

__global__ void k_init_ph(const float* __restrict__ ang) {
    int i = blockIdx.x * blockDim.x + threadIdx.x;
    if (i < TOTF) {
        float s, c;
        sincosf(ang[i], &s, &c);
        g_ph[i] = make_float2(c, s);
    }
}

__global__ void k_zero_y(float4* __restrict__ y4) {
    int i = blockIdx.x * blockDim.x + threadIdx.x;
    if (i < (BVAL * OUTLEN) / 4) y4[i] = make_float4(0.f, 0.f, 0.f, 0.f);
}

// ---------------------------------------------------------------------------
// ISTFT (init only): spec = mag * phasor -> irfft -> window -> v2-red OLA
// ---------------------------------------------------------------------------
__global__ __launch_bounds__(256) void k_istft(const float* __restrict__ mag,
                                               float* __restrict__ y) {
    __shared__ float2 sw[8][SBUF];
    const int wid = threadIdx.x >> 5;
    const int l   = threadIdx.x & 31;
    const int frame = (blockIdx.x << 3) + wid;
    const int b = frame >> 10;
    const int t = frame & 1023;
    const float*  magp = mag  + (size_t)frame * FBINS;
    const float2* php  = g_ph + (size_t)frame * FBINS;

    float2 v[8];
#pragma unroll
    for (int j = 0; j < 8; j++) {
        int k  = l + (j << 5);
        int kr = 256 - k;
        float  mk = magp[k];
        float  mr = magp[kr];
        float2 pk = php[k];
        float2 pr = php[kr];
        float Xkx = mk * pk.x, Xky = mk * pk.y;
        float Xcx = mr * pr.x, Xcy = -mr * pr.y;   // conj(X[256-k])
        if (k == 0) { Xky = 0.f; Xcy = 0.f; }
        float Zex = 0.5f * (Xkx + Xcx), Zey = 0.5f * (Xky + Xcy);
        float Bx  = 0.5f * (Xkx - Xcx), By  = 0.5f * (Xky - Xcy);
        float2 e = g_pk[k];
        float Zox = Bx * e.x - By * e.y;
        float Zoy = Bx * e.y + By * e.x;
        v[j] = make_float2(Zex - Zoy, Zey + Zox);
    }
    fft256_warp<1>(v, l);

    const int r8 = brev5(l) << 3;
#pragma unroll
    for (int j = 0; j < 8; j++) sw[wid][IDXP(j + r8)] = v[j];
    __syncwarp();

    float* yb = y + (size_t)b * OUTLEN + t * HOPSZ;
#pragma unroll
    for (int j = 0; j < 8; j++) {
        int m = l + (j << 5);
        float2 z = sw[wid][IDXP(m)];
        float2 w = g_wsc[m];
        red_add_v2(yb + 2 * m, z.x * w.x, z.y * w.y);
    }
}

// ---------------------------------------------------------------------------
// Fused Griffin-Lim step, one frame per warp:
// gather(y_src) -> rfft -> phase+remag (registers) -> irfft -> scatter(y_dst)
// ---------------------------------------------------------------------------
__device__ __forceinline__ float sample_at(const float* yb, int i) {
    int j = i - PADN;
    j = (j < 0) ? -j : j;
    if (j >= LTRIM) j = 2 * LTRIM - 2 - j;
    int idx = j + PADN;
    return yb[idx] * g_invwsq[idx];
}

__device__ __forceinline__ float2 scaled_norm(float x, float y, float m) {
    float m2 = x * x + y * y;
    if (m2 < 1e-30f) return make_float2(m, 0.f);  // atan2(0,0)=0 -> phase (1,0)
    float inv = m * rsqrtf(m2);
    return make_float2(x * inv, y * inv);
}

__global__ __launch_bounds__(256) void k_gl_step(const float* __restrict__ mag,
                                                 const float* __restrict__ win,
                                                 const float* __restrict__ ysrc,
                                                 float* __restrict__ ydst) {
    __shared__ float2 sw[8][SBUF];
    const int wid = threadIdx.x >> 5;
    const int l   = threadIdx.x & 31;
    const int frame = (blockIdx.x << 3) + wid;
    const int b = frame >> 10;
    const int t = frame & 1023;
    const float* magp = mag + (size_t)frame * FBINS;
    const float* ysb  = ysrc + (size_t)b * OUTLEN;
    const int i0 = t * HOPSZ;
    const float2* w2p = (const float2*)win;

    // ---- STFT gather (fast path for interior frames) ----
    float2 v[8];
    if (t >= 2 && t <= 1021) {
        const float2* src = (const float2*)(ysb + i0);
        const float2* iwp = (const float2*)(g_invwsq + i0);
#pragma unroll
        for (int j = 0; j < 8; j++) {
            int m = l + (j << 5);
            float2 xy = src[m];
            float2 iw = iwp[m];
            float2 w  = w2p[m];
            v[j] = make_float2(xy.x * iw.x * w.x, xy.y * iw.y * w.y);
        }
    } else {
#pragma unroll
        for (int j = 0; j < 8; j++) {
            int m  = l + (j << 5);
            int n0 = 2 * m;
            float x0 = sample_at(ysb, i0 + n0);
            float x1 = sample_at(ysb, i0 + n0 + 1);
            float2 w = w2p[m];
            v[j] = make_float2(x0 * w.x, x1 * w.y);
        }
    }
    fft256_warp<-1>(v, l);   // forward

    const int r8 = brev5(l) << 3;
#pragma unroll
    for (int j = 0; j < 8; j++) sw[wid][IDXP(j + r8)] = v[j];
    __syncwarp();

    // ---- phase + re-magnitude + inverse pack, all in registers ----
    // S = Ze + Zo*conj(e) = X[k] ; D = Ze - Zo*conj(e) = conj(X[256-k])
    // A = mag[k]*S/|S| ; C = mag[256-k]*D/|D|
    // Z'[k] = Pe + i*(B*e), Pe = (A+C)/2, B = (A-C)/2
#pragma unroll
    for (int j = 0; j < 8; j++) {
        int k = l + (j << 5);
        if (k == 0) {
            float2 Z0 = sw[wid][IDXP(0)];
            float X0 = Z0.x + Z0.y;       // X[0]   (real)
            float XN = Z0.x - Z0.y;       // X[256] (real)
            float A = (X0 >= 0.f) ? magp[0]   : -magp[0];
            float C = (XN >= 0.f) ? magp[256] : -magp[256];
            v[j] = make_float2(0.5f * (A + C), 0.5f * (A - C));
        } else {
            float2 Zk = sw[wid][IDXP(k)];
            float2 Zr = sw[wid][IDXP(256 - k)];
            float Zex = 0.5f * (Zk.x + Zr.x);
            float Zey = 0.5f * (Zk.y - Zr.y);
            float Zox = 0.5f * (Zk.y + Zr.y);
            float Zoy = -0.5f * (Zk.x - Zr.x);
            float2 e = g_pk[k];
            float Tx = Zox * e.x + Zoy * e.y;     // Zo * conj(e)
            float Ty = Zoy * e.x - Zox * e.y;
            float2 A = scaled_norm(Zex + Tx, Zey + Ty, magp[k]);
            float2 C = scaled_norm(Zex - Tx, Zey - Ty, magp[256 - k]);
            float Pex = 0.5f * (A.x + C.x), Pey = 0.5f * (A.y + C.y);
            float Bx  = 0.5f * (A.x - C.x), By  = 0.5f * (A.y - C.y);
            float Qx = Bx * e.x - By * e.y;
            float Qy = Bx * e.y + By * e.x;
            v[j] = make_float2(Pex - Qy, Pey + Qx);
        }
    }
    __syncwarp();   // all sw reads done before overwrite below

    fft256_warp<1>(v, l);   // inverse, unnormalized

#pragma unroll
    for (int j = 0; j < 8; j++) sw[wid][IDXP(j + r8)] = v[j];
    __syncwarp();

    float* yd = ydst + (size_t)b * OUTLEN + t * HOPSZ;
#pragma unroll
    for (int j = 0; j < 8; j++) {
        int m = l + (j << 5);
        float2 z = sw[wid][IDXP(m)];
        float2 w = g_wsc[m];
        red_add_v2(yd + 2 * m, z.x * w.x, z.y * w.y);
    }
}

__global__ void k_out(const float* __restrict__ y, float* __restrict__ out) {
    int i = blockIdx.x * blockDim.x + threadIdx.x;
    if (i < BVAL * LTRIM) {
        int b = i / LTRIM;
        int r = i - b * LTRIM;
        int idx = PADN + r;
        out[i] = y[(size_t)b * OUTLEN + idx] * g_invwsq[idx];
    }
}

// ---------------------------------------------------------------------------
extern "C" void kernel_launch(void* const* d_in, const int* in_sizes, int n_in,
                              void* d_out, int out_size) {
    const float* mag = (const float*)d_in[0];   // [32,1024,257]
    const float* ang = (const float*)d_in[1];   // [32,1024,257]
    const float* win = (const float*)d_in[2];   // [512]
    float* out = (float*)d_out;                 // [32,163680]

    float* ya;  cudaGetSymbolAddress((void**)&ya, g_ya4);
    float* yb;  cudaGetSymbolAddress((void**)&yb, g_yb4);

    k_tables<<<1, FBINS>>>();
    k_invwsq<<<(OUTLEN + 255) / 256, 256>>>(win);
    k_init_ph<<<TOTF / 256, 256>>>(ang);

    const int zgrid = ((BVAL * OUTLEN) / 4 + 255) / 256;
    const int fgrid = NFRAMES / 8;   // 8 frames (warps) per block

    k_zero_y<<<zgrid, 256>>>((float4*)ya);
    k_istft<<<fgrid, 256>>>(mag, ya);          // y_0 = istft(mag * e^{i*ang})

    for (int it = 0; it < NITER; it++) {
        float* src = (it & 1) ? yb : ya;
        float* dst = (it & 1) ? ya : yb;
        k_zero_y<<<zgrid, 256>>>((float4*)dst);
        k_gl_step<<<fgrid, 256>>>(mag, win, src, dst);
    }
    // NITER=32 even -> final waveform lands in ya
    k_out<<<(BVAL * LTRIM + 255) / 256, 256>>>(ya, out);
}

// round 16
// speedup vs baseline: 1.6079x; 1.0017x over previous
#include <cuda_runtime.h>
#include <cstdint>

#define NFFT   512
#define HOPSZ  160
#define PADN   256
#define BVAL   32
#define TVAL   1024
#define FBINS  257
#define LTRIM  163680                  // (TVAL-1)*HOPSZ
#define OUTLEN 164192                  // NFFT + HOPSZ*(TVAL-1)
#define NITER  32
#define TOTF   (BVAL*TVAL*FBINS)       // 8421376
#define NFRAMES (BVAL*TVAL)            // 32768
#define PI_F 3.14159265358979323846f
#define RSQ2 0.70710678118654752440f

// ---------------- scratch (device globals; no allocation allowed) ------------
__device__ float4 g_ya4[(BVAL * OUTLEN) / 4];          // waveform ping (raw), 21 MB
__device__ float4 g_yb4[(BVAL * OUTLEN) / 4];          // waveform pong (raw), 21 MB
__device__ float2 g_ph[TOTF];                          // init phasor fp32, 67 MB
__device__ float  g_invwsq[OUTLEN];                    // NOLA 1/wsq (guarded)
__device__ float2 g_wsc[256];                          // win/256 pairs (scatter)
__device__ float2 g_wq[256];                           // win*invwsq pairs (gather, interior)
__device__ float2 g_tw[256];                           // e^{+2*pi*i*k/256}
__device__ float2 g_pk[FBINS];                         // (cos(pi k/256), sin(pi k/256))

__device__ __forceinline__ float2 cmulf(float2 a, float2 b) {
    return make_float2(a.x * b.x - a.y * b.y, a.x * b.y + a.y * b.x);
}
__device__ __forceinline__ float2 cadd(float2 a, float2 b) {
    return make_float2(a.x + b.x, a.y + b.y);
}
__device__ __forceinline__ float2 csub(float2 a, float2 b) {
    return make_float2(a.x - b.x, a.y - b.y);
}
template <int SGN>
__device__ __forceinline__ float2 cmuli(float2 a) {   // SGN * i * a
    return (SGN > 0) ? make_float2(-a.y, a.x) : make_float2(a.y, -a.x);
}

// one red.global.add.v2.f32 instead of two scalar atomics (addr 8B-aligned)
__device__ __forceinline__ void red_add_v2(float* addr, float x, float y) {
    asm volatile("red.global.add.v2.f32 [%0], {%1, %2};"
                 :: "l"(addr), "f"(x), "f"(y) : "memory");
}

// padded smem index: +1 float2 every 16 to break stride-8/16 conflicts
#define IDXP(i) ((i) + ((i) >> 4))
#define SBUF 272

// ---------------------------------------------------------------------------
// 256-pt complex FFT, one warp per transform, 8 complex points per lane.
// Input:  v[j] = x[l + 32*j] (natural order); Output: v[j] = X[j + 8*brev5(l)]
// SGN = -1 forward, +1 inverse (unnormalized). Cross-lane 32-pt FFT:
// fused radix-4/radix-4/radix-2 with deferred twiddles (2 cmul rounds).
// ---------------------------------------------------------------------------
template <int SGN>
__device__ __forceinline__ void fft256_warp(float2 v[8], int l) {
    // ---- radix-8 over j (stride-32 dim), registers ----
    float2 t0 = v[0], t1 = v[4], t2 = v[2], t3 = v[6];
    float2 t4 = v[1], t5 = v[5], t6 = v[3], t7 = v[7];
    float2 a0 = cadd(t0, t1), a1 = csub(t0, t1);
    float2 a2 = cadd(t2, t3), a3 = csub(t2, t3);
    float2 a4 = cadd(t4, t5), a5 = csub(t4, t5);
    float2 a6 = cadd(t6, t7), a7 = csub(t6, t7);
    float2 i3 = cmuli<SGN>(a3), i7 = cmuli<SGN>(a7);
    float2 b0 = cadd(a0, a2), b2 = csub(a0, a2);
    float2 b1 = cadd(a1, i3), b3 = csub(a1, i3);
    float2 b4 = cadd(a4, a6), b6 = csub(a4, a6);
    float2 b5 = cadd(a5, i7), b7 = csub(a5, i7);
    float2 u1 = make_float2(RSQ2 * (b5.x - (float)SGN * b5.y),
                            RSQ2 * (b5.y + (float)SGN * b5.x));
    float2 u2 = cmuli<SGN>(b6);
    float2 u3 = make_float2(-RSQ2 * (b7.x + (float)SGN * b7.y),
                             RSQ2 * ((float)SGN * b7.x - b7.y));
    v[0] = cadd(b0, b4);  v[4] = csub(b0, b4);
    v[1] = cadd(b1, u1);  v[5] = csub(b1, u1);
    v[2] = cadd(b2, u2);  v[6] = csub(b2, u2);
    v[3] = cadd(b3, u3);  v[7] = csub(b3, u3);

    // ---- twiddle e^{SGN*2*pi*i*l*k1/256} via power chain ----
    float2 w1 = g_tw[l];
    if (SGN < 0) w1.y = -w1.y;
    float2 w = w1;
    v[1] = cmulf(v[1], w);
#pragma unroll
    for (int k1 = 2; k1 < 8; k1++) {
        w = cmulf(w, w1);
        v[k1] = cmulf(v[k1], w);
    }

    // ---- cross-lane 32-pt FFT: 5 xor-shfl rounds, 2 cmul rounds ----
    const int lb4 = (l >> 4) & 1, lb3 = (l >> 3) & 1;
    const int lb2 = (l >> 2) & 1, lb1 = (l >> 1) & 1, lb0 = l & 1;

    {   // Round 1: xor 16; lanes (b4&b3) pick up W32^8 = SGN*i
        const float p = lb4 ? -1.f : 1.f;
        const bool rot = (lb4 & lb3) != 0;
#pragma unroll
        for (int j = 0; j < 8; j++) {
            float2 o = v[j];
            float tx = __shfl_xor_sync(0xffffffffu, o.x, 16);
            float ty = __shfl_xor_sync(0xffffffffu, o.y, 16);
            float2 q = make_float2(tx + p * o.x, ty + p * o.y);
            v[j] = rot ? cmuli<SGN>(q) : q;
        }
    }
    {   // Round 2: xor 8; combined twiddle W32^{(l&7)*e1}, e1 = b4+2*b3
        const float p = lb3 ? -1.f : 1.f;
        const int e1 = lb4 + 2 * lb3;
        float2 tw = g_tw[((l & 7) * e1) << 3];
        if (SGN < 0) tw.y = -tw.y;
#pragma unroll
        for (int j = 0; j < 8; j++) {
            float2 o = v[j];
            float tx = __shfl_xor_sync(0xffffffffu, o.x, 8);
            float ty = __shfl_xor_sync(0xffffffffu, o.y, 8);
            float2 q = make_float2(tx + p * o.x, ty + p * o.y);
            v[j] = cmulf(q, tw);
        }
    }
    {   // Round 3: xor 4; lanes (b2&b1) pick up W8^2 = SGN*i
        const float p = lb2 ? -1.f : 1.f;
        const bool rot = (lb2 & lb1) != 0;
#pragma unroll
        for (int j = 0; j < 8; j++) {
            float2 o = v[j];
            float tx = __shfl_xor_sync(0xffffffffu, o.x, 4);
            float ty = __shfl_xor_sync(0xffffffffu, o.y, 4);
            float2 q = make_float2(tx + p * o.x, ty + p * o.y);
            v[j] = rot ? cmuli<SGN>(q) : q;
        }
    }
    {   // Round 4: xor 2; combined twiddle W8^{b0*e2}, e2 = b2+2*b1
        const float p = lb1 ? -1.f : 1.f;
        const int e2 = lb2 + 2 * lb1;
        float2 tw = g_tw[(lb0 * e2) << 5];
        if (SGN < 0) tw.y = -tw.y;
#pragma unroll
        for (int j = 0; j < 8; j++) {
            float2 o = v[j];
            float tx = __shfl_xor_sync(0xffffffffu, o.x, 2);
            float ty = __shfl_xor_sync(0xffffffffu, o.y, 2);
            float2 q = make_float2(tx + p * o.x, ty + p * o.y);
            v[j] = cmulf(q, tw);
        }
    }
    {   // Round 5: xor 1, no twiddle
        const float p = lb0 ? -1.f : 1.f;
#pragma unroll
        for (int j = 0; j < 8; j++) {
            float2 o = v[j];
            float tx = __shfl_xor_sync(0xffffffffu, o.x, 1);
            float ty = __shfl_xor_sync(0xffffffffu, o.y, 1);
            v[j] = make_float2(tx + p * o.x, ty + p * o.y);
        }
    }
}

__device__ __forceinline__ int brev5(int l) { return (int)(__brev((unsigned)l) >> 27); }

// ---------------------------------------------------------------------------
__global__ void k_tables() {
    int k = threadIdx.x;
    if (k < 256) {
        float a = (2.0f * PI_F) * (float)k / 256.0f;
        g_tw[k] = make_float2(cosf(a), sinf(a));
    }
    if (k < FBINS) {
        float b = PI_F * (float)k / 256.0f;
        g_pk[k] = make_float2(cosf(b), sinf(b));
    }
}

__device__ __forceinline__ float wsq_at(const float* win, int p) {
    int tmax = p / HOPSZ;             if (tmax > TVAL - 1) tmax = TVAL - 1;
    int tmin = (p - (NFFT - 1) + HOPSZ - 1) / HOPSZ;  if (tmin < 0) tmin = 0;
    float s = 0.f;
    for (int t = tmin; t <= tmax; t++) {
        int n = p - t * HOPSZ;
        if (n >= 0 && n < NFFT) { float w = win[n]; s += w * w; }
    }
    return s;
}

__global__ void k_invwsq(const float* __restrict__ win) {
    int i = blockIdx.x * blockDim.x + threadIdx.x;
    if (i < 256) {  // prescaled scatter window: win/256 as float2 pairs
        g_wsc[i] = make_float2(win[2 * i] * (1.0f / 256.0f),
                               win[2 * i + 1] * (1.0f / 256.0f));
        // gather table for interior frames: wq[n] = win[n] * 1/wsq(640+n)
        // (wsq is HOP-periodic on [512,163839]; 640 = 4*HOP is canonical)
        float s0 = wsq_at(win, 640 + 2 * i);
        float s1 = wsq_at(win, 641 + 2 * i);
        float iw0 = (s0 > 1e-11f) ? (1.0f / s0) : 1.0f;
        float iw1 = (s1 > 1e-11f) ? (1.0f / s1) : 1.0f;
        g_wq[i] = make_float2(win[2 * i] * iw0, win[2 * i + 1] * iw1);
    }
    if (i >= OUTLEN) return;
    float s = wsq_at(win, i);
    g_invwsq[i] = (s > 1e-11f) ? (1.0f / s) : 1.0f;
}

__global__ void k_init_ph(const float* __restrict__ ang) {
    int i = blockIdx.x * blockDim.x + threadIdx.x;
    if (i < TOTF) {
        float s, c;
        sincosf(ang[i], &s, &c);
        g_ph[i] = make_float2(c, s);
    }
}

__global__ void k_zero_y(float4* __restrict__ y4) {
    int i = blockIdx.x * blockDim.x + threadIdx.x;
    if (i < (BVAL * OUTLEN) / 4) y4[i] = make_float4(0.f, 0.f, 0.f, 0.f);
}

// ---------------------------------------------------------------------------
// ISTFT (init only): spec = mag * phasor -> irfft -> window -> v2-red OLA
// ---------------------------------------------------------------------------
__global__ __launch_bounds__(256, 6) void k_istft(const float* __restrict__ mag,
                                                  float* __restrict__ y) {
    __shared__ float2 sw[8][SBUF];
    const int wid = threadIdx.x >> 5;
    const int l   = threadIdx.x & 31;
    const int frame = (blockIdx.x << 3) + wid;
    const int b = frame >> 10;
    const int t = frame & 1023;
    const float*  magp = mag  + (size_t)frame * FBINS;
    const float2* php  = g_ph + (size_t)frame * FBINS;

    float2 v[8];
#pragma unroll
    for (int j = 0; j < 8; j++) {
        int k  = l + (j << 5);
        int kr = 256 - k;
        float  mk = magp[k];
        float  mr = magp[kr];
        float2 pk = php[k];
        float2 pr = php[kr];
        float Xkx = mk * pk.x, Xky = mk * pk.y;
        float Xcx = mr * pr.x, Xcy = -mr * pr.y;   // conj(X[256-k])
        if (k == 0) { Xky = 0.f; Xcy = 0.f; }
        float Zex = 0.5f * (Xkx + Xcx), Zey = 0.5f * (Xky + Xcy);
        float Bx  = 0.5f * (Xkx - Xcx), By  = 0.5f * (Xky - Xcy);
        float2 e = g_pk[k];
        float Zox = Bx * e.x - By * e.y;
        float Zoy = Bx * e.y + By * e.x;
        v[j] = make_float2(Zex - Zoy, Zey + Zox);
    }
    fft256_warp<1>(v, l);

    const int r8 = brev5(l) << 3;
#pragma unroll
    for (int j = 0; j < 8; j++) sw[wid][IDXP(j + r8)] = v[j];
    __syncwarp();

    float* yb = y + (size_t)b * OUTLEN + t * HOPSZ;
#pragma unroll
    for (int j = 0; j < 8; j++) {
        int m = l + (j << 5);
        float2 z = sw[wid][IDXP(m)];
        float2 w = g_wsc[m];
        red_add_v2(yb + 2 * m, z.x * w.x, z.y * w.y);
    }
}

// ---------------------------------------------------------------------------
// Fused Griffin-Lim step, one frame per warp:
// gather(y_src) -> rfft -> phase+remag (registers) -> irfft -> scatter(y_dst)
// ---------------------------------------------------------------------------
__device__ __forceinline__ float sample_at(const float* yb, int i) {
    int j = i - PADN;
    j = (j < 0) ? -j : j;
    if (j >= LTRIM) j = 2 * LTRIM - 2 - j;
    int idx = j + PADN;
    return yb[idx] * g_invwsq[idx];
}

__device__ __forceinline__ float2 scaled_norm(float x, float y, float m) {
    float m2 = x * x + y * y;
    if (m2 < 1e-30f) return make_float2(m, 0.f);  // atan2(0,0)=0 -> phase (1,0)
    float inv = m * rsqrtf(m2);
    return make_float2(x * inv, y * inv);
}

__global__ __launch_bounds__(256, 6) void k_gl_step(const float* __restrict__ mag,
                                                    const float* __restrict__ win,
                                                    const float* __restrict__ ysrc,
                                                    float* __restrict__ ydst) {
    __shared__ float2 sw[8][SBUF];
    const int wid = threadIdx.x >> 5;
    const int l   = threadIdx.x & 31;
    const int frame = (blockIdx.x << 3) + wid;
    const int b = frame >> 10;
    const int t = frame & 1023;
    const float* magp = mag + (size_t)frame * FBINS;
    const float* ysb  = ysrc + (size_t)b * OUTLEN;
    const int i0 = t * HOPSZ;
    const float2* w2p = (const float2*)win;

    // ---- STFT gather ----
    // Interior frames t in [4,1020]: no reflection possible AND wsq is
    // HOP-periodic there, so invwsq[i0+n] == invwsq[640+n] -> folded table wq.
    float2 v[8];
    if (t >= 4 && t <= 1020) {
        const float2* src = (const float2*)(ysb + i0);
#pragma unroll
        for (int j = 0; j < 8; j++) {
            int m = l + (j << 5);
            float2 xy = src[m];
            float2 wq = g_wq[m];
            v[j] = make_float2(xy.x * wq.x, xy.y * wq.y);
        }
    } else {
#pragma unroll
        for (int j = 0; j < 8; j++) {
            int m  = l + (j << 5);
            int n0 = 2 * m;
            float x0 = sample_at(ysb, i0 + n0);
            float x1 = sample_at(ysb, i0 + n0 + 1);
            float2 w = w2p[m];
            v[j] = make_float2(x0 * w.x, x1 * w.y);
        }
    }
    fft256_warp<-1>(v, l);   // forward

    const int r8 = brev5(l) << 3;
#pragma unroll
    for (int j = 0; j < 8; j++) sw[wid][IDXP(j + r8)] = v[j];
    __syncwarp();

    // ---- phase + re-magnitude + inverse pack, all in registers ----
    // S = Ze + Zo*conj(e) = X[k] ; D = Ze - Zo*conj(e) = conj(X[256-k])
    // A = mag[k]*S/|S| ; C = mag[256-k]*D/|D|
    // Z'[k] = Pe + i*(B*e), Pe = (A+C)/2, B = (A-C)/2
#pragma unroll
    for (int j = 0; j < 8; j++) {
        int k = l + (j << 5);
        if (k == 0) {
            float2 Z0 = sw[wid][IDXP(0)];
            float X0 = Z0.x + Z0.y;       // X[0]   (real)
            float XN = Z0.x - Z0.y;       // X[256] (real)
            float A = (X0 >= 0.f) ? magp[0]   : -magp[0];
            float C = (XN >= 0.f) ? magp[256] : -magp[256];
            v[j] = make_float2(0.5f * (A + C), 0.5f * (A - C));
        } else {
            float2 Zk = sw[wid][IDXP(k)];
            float2 Zr = sw[wid][IDXP(256 - k)];
            float Zex = 0.5f * (Zk.x + Zr.x);
            float Zey = 0.5f * (Zk.y - Zr.y);
            float Zox = 0.5f * (Zk.y + Zr.y);
            float Zoy = -0.5f * (Zk.x - Zr.x);
            float2 e = g_pk[k];
            float Tx = Zox * e.x + Zoy * e.y;     // Zo * conj(e)
            float Ty = Zoy * e.x - Zox * e.y;
            float2 A = scaled_norm(Zex + Tx, Zey + Ty, magp[k]);
            float2 C = scaled_norm(Zex - Tx, Zey - Ty, magp[256 - k]);
            float Pex = 0.5f * (A.x + C.x), Pey = 0.5f * (A.y + C.y);
            float Bx  = 0.5f * (A.x - C.x), By  = 0.5f * (A.y - C.y);
            float Qx = Bx * e.x - By * e.y;
            float Qy = Bx * e.y + By * e.x;
            v[j] = make_float2(Pex - Qy, Pey + Qx);
        }
    }
    __syncwarp();   // all sw reads done before overwrite below

    fft256_warp<1>(v, l);   // inverse, unnormalized

#pragma unroll
    for (int j = 0; j < 8; j++) sw[wid][IDXP(j + r8)] = v[j];
    __syncwarp();

    float* yd = ydst + (size_t)b * OUTLEN + t * HOPSZ;
#pragma unroll
    for (int j = 0; j < 8; j++) {
        int m = l + (j << 5);
        float2 z = sw[wid][IDXP(m)];
        float2 w = g_wsc[m];
        red_add_v2(yd + 2 * m, z.x * w.x, z.y * w.y);
    }
}

__global__ void k_out(const float* __restrict__ y, float* __restrict__ out) {
    int i = blockIdx.x * blockDim.x + threadIdx.x;
    if (i < BVAL * LTRIM) {
        int b = i / LTRIM;
        int r = i - b * LTRIM;
        int idx = PADN + r;
        out[i] = y[(size_t)b * OUTLEN + idx] * g_invwsq[idx];
    }
}

// ---------------------------------------------------------------------------
extern "C" void kernel_launch(void* const* d_in, const int* in_sizes, int n_in,
                              void* d_out, int out_size) {
    const float* mag = (const float*)d_in[0];   // [32,1024,257]
    const float* ang = (const float*)d_in[1];   // [32,1024,257]
    const float* win = (const float*)d_in[2];   // [512]
    float* out = (float*)d_out;                 // [32,163680]

    float* ya;  cudaGetSymbolAddress((void**)&ya, g_ya4);
    float* yb;  cudaGetSymbolAddress((void**)&yb, g_yb4);

    k_tables<<<1, FBINS>>>();
    k_invwsq<<<(OUTLEN + 255) / 256, 256>>>(win);
    k_init_ph<<<TOTF / 256, 256>>>(ang);

    const int zgrid = ((BVAL * OUTLEN) / 4 + 255) / 256;
    const int fgrid = NFRAMES / 8;   // 8 frames (warps) per block

    k_zero_y<<<zgrid, 256>>>((float4*)ya);
    k_istft<<<fgrid, 256>>>(mag, ya);          // y_0 = istft(mag * e^{i*ang})

    for (int it = 0; it < NITER; it++) {
        float* src = (it & 1) ? yb : ya;
        float* dst = (it & 1) ? ya : yb;
        k_zero_y<<<zgrid, 256>>>((float4*)dst);
        k_gl_step<<<fgrid, 256>>>(mag, win, src, dst);
    }
    // NITER=32 even -> final waveform lands in ya
    k_out<<<(BVAL * LTRIM + 255) / 256, 256>>>(ya, out);
}